// round 15
// baseline (speedup 1.0000x reference)
#include <cuda_runtime.h>
#include <cuda_bf16.h>
#include <cstdint>

// Problem constants
#define BB     8
#define LL     1024
#define HEADS  4
#define KD     128
#define EMB    512
#define NREL   63

// ---------------------------------------------------------------------------
// Device-global scratch (no allocations allowed)
// ---------------------------------------------------------------------------
__device__ float          g_rwh[32*1024*128];        // fused RW|RH bias, pitch 128
__device__ __nv_bfloat16  g_xh [BB*LL*EMB], g_xl [BB*LL*EMB];
__device__ __nv_bfloat16  g_qh [BB*LL*EMB], g_ql [BB*LL*EMB];
__device__ __nv_bfloat16  g_kh [BB*LL*EMB], g_kl [BB*LL*EMB];
__device__ __nv_bfloat16  g_vh [BB*LL*EMB], g_vl [BB*LL*EMB];
__device__ __nv_bfloat16  g_aoh[BB*LL*EMB], g_aol[BB*LL*EMB];
__device__ __nv_bfloat16  g_wqh[EMB*EMB], g_wql[EMB*EMB];
__device__ __nv_bfloat16  g_wkh[EMB*EMB], g_wkl[EMB*EMB];
__device__ __nv_bfloat16  g_wvh[EMB*EMB], g_wvl[EMB*EMB];
__device__ __nv_bfloat16  g_woh[EMB*EMB], g_wol[EMB*EMB];
__device__ __nv_bfloat16  g_pbh[128*128], g_pbl[128*128];   // padded [posW|posH]^T

// ---------------------------------------------------------------------------
// PTX helpers
// ---------------------------------------------------------------------------
__device__ __forceinline__ uint32_t smem_u32(const void* p) {
    uint32_t a;
    asm("{ .reg .u64 t; cvta.to.shared.u64 t, %1; cvt.u32.u64 %0, t; }" : "=r"(a) : "l"(p));
    return a;
}
__device__ __forceinline__ void ldsm4(uint32_t addr, uint32_t* r) {
    asm volatile("ldmatrix.sync.aligned.m8n8.x4.shared.b16 {%0,%1,%2,%3}, [%4];"
                 : "=r"(r[0]), "=r"(r[1]), "=r"(r[2]), "=r"(r[3]) : "r"(addr));
}
__device__ __forceinline__ void ldsm4t(uint32_t addr, uint32_t* r) {
    asm volatile("ldmatrix.sync.aligned.m8n8.x4.trans.shared.b16 {%0,%1,%2,%3}, [%4];"
                 : "=r"(r[0]), "=r"(r[1]), "=r"(r[2]), "=r"(r[3]) : "r"(addr));
}
__device__ __forceinline__ void mma_bf16(float* d, const uint32_t* a, uint32_t b0, uint32_t b1) {
    asm volatile("mma.sync.aligned.m16n8k16.row.col.f32.bf16.bf16.f32 "
                 "{%0,%1,%2,%3}, {%4,%5,%6,%7}, {%8,%9}, {%0,%1,%2,%3};"
                 : "+f"(d[0]), "+f"(d[1]), "+f"(d[2]), "+f"(d[3])
                 : "r"(a[0]), "r"(a[1]), "r"(a[2]), "r"(a[3]), "r"(b0), "r"(b1));
}
#define CP_ASYNC(dst, src) asm volatile("cp.async.ca.shared.global [%0], [%1], 16;" :: "r"(dst), "l"(src))
#define CP_COMMIT()        asm volatile("cp.async.commit_group;" ::: "memory")
#define CP_WAIT1()         asm volatile("cp.async.wait_group 1;" ::: "memory")
#define CP_WAIT0()         asm volatile("cp.async.wait_group 0;" ::: "memory")

__device__ __forceinline__ void bsplit(float x, __nv_bfloat16& h, __nv_bfloat16& l) {
    h = __float2bfloat16_rn(x);
    l = __float2bfloat16_rn(x - __bfloat162float(h));
}
__device__ __forceinline__ uint32_t packbf(__nv_bfloat16 a, __nv_bfloat16 b) {
    __nv_bfloat162 t(a, b);
    return *(uint32_t*)&t;
}

// ---------------------------------------------------------------------------
// Shared GEMM machinery constants (2-stage: 80 KB -> 2 CTAs/SM)
// ---------------------------------------------------------------------------
#define STG_BYTES 40960
#define TILE_P    10240
#define GEMM_SMEM (2 * STG_BYTES)

// ---------------------------------------------------------------------------
// bf16-split pipelined mma GEMM (generic, fp32 out): C = (A@B^T)*scale
// ---------------------------------------------------------------------------
__global__ __launch_bounds__(256, 2) void gemm_bs(
    const __nv_bfloat16* __restrict__ Ahi, const __nv_bfloat16* __restrict__ Alo,
    int lda, long long strA1, long long strA2,
    const __nv_bfloat16* __restrict__ Bhi, const __nv_bfloat16* __restrict__ Blo,
    int ldb, long long strB1, long long strB2,
    float* __restrict__ Cf,
    int ldc, long long strC1, long long strC2,
    int kIters, float scale)
{
    extern __shared__ char smem[];
    const uint32_t sb0 = smem_u32(smem);
    const int tid  = threadIdx.x;
    const int lane = tid & 31;
    const int wid  = tid >> 5;
    const int wm   = wid >> 1;
    const int wn   = wid & 1;
    const int n0   = blockIdx.x * 128;
    const int m0   = blockIdx.y * 128;
    const int z    = blockIdx.z;

    const size_t offA = (size_t)(z >> 2) * strA1 + (size_t)(z & 3) * strA2;
    const size_t offB = (size_t)(z >> 2) * strB1 + (size_t)(z & 3) * strB2;
    const size_t offC = (size_t)(z >> 2) * strC1 + (size_t)(z & 3) * strC2;

    const __nv_bfloat16* aH = Ahi + offA + (size_t)m0 * lda;
    const __nv_bfloat16* aL = Alo + offA + (size_t)m0 * lda;
    const __nv_bfloat16* bH = Bhi + offB + (size_t)n0 * ldb;
    const __nv_bfloat16* bL = Blo + offB + (size_t)n0 * ldb;

    auto issue = [&](int c, int stg) {
        const uint32_t sb = sb0 + stg * STG_BYTES;
        const int k0 = c * 32;
#pragma unroll
        for (int i = 0; i < 2; i++) {
            int o  = tid + i * 256;
            int r  = o >> 2;
            int ch = o & 3;
            uint32_t d = sb + r * 80 + ch * 16;
            const __nv_bfloat16* s;
            s = aH + (size_t)r * lda + k0 + ch * 8; CP_ASYNC(d,            s);
            s = aL + (size_t)r * lda + k0 + ch * 8; CP_ASYNC(d + TILE_P,   s);
            s = bH + (size_t)r * ldb + k0 + ch * 8; CP_ASYNC(d + 2*TILE_P, s);
            s = bL + (size_t)r * ldb + k0 + ch * 8; CP_ASYNC(d + 3*TILE_P, s);
        }
        CP_COMMIT();
    };

    issue(0, 0);
    if (kIters > 1) issue(1, 1);

    float acc[2][8][4];
#pragma unroll
    for (int mt = 0; mt < 2; mt++)
#pragma unroll
        for (int nt = 0; nt < 8; nt++)
#pragma unroll
            for (int e = 0; e < 4; e++) acc[mt][nt][e] = 0.f;

    for (int c = 0; c < kIters; c++) {
        CP_WAIT1();
        __syncthreads();

        const uint32_t sb = sb0 + (c & 1) * STG_BYTES;
#pragma unroll
        for (int s = 0; s < 2; s++) {
            uint32_t ahf[2][4], alf[2][4];
#pragma unroll
            for (int mt = 0; mt < 2; mt++) {
                uint32_t addr = sb + (uint32_t)((wm * 32 + mt * 16 + (lane & 15)) * 80)
                                   + (uint32_t)((s * 2 + (lane >> 4)) << 4);
                ldsm4(addr,          ahf[mt]);
                ldsm4(addr + TILE_P, alf[mt]);
            }
#pragma unroll
            for (int ng = 0; ng < 4; ng++) {
                int row = wn * 64 + ng * 16 + ((lane >> 4) << 3) + (lane & 7);
                uint32_t addr = sb + 2 * TILE_P + (uint32_t)(row * 80)
                                   + (uint32_t)((s * 2 + ((lane >> 3) & 1)) << 4);
                uint32_t bhf[4], blf[4];
                ldsm4(addr,          bhf);
                ldsm4(addr + TILE_P, blf);
#pragma unroll
                for (int hf = 0; hf < 2; hf++) {
                    int nt = ng * 2 + hf, o = hf * 2;
#pragma unroll
                    for (int mt = 0; mt < 2; mt++) {
                        mma_bf16(acc[mt][nt], ahf[mt], bhf[o], bhf[o + 1]);
                        mma_bf16(acc[mt][nt], ahf[mt], blf[o], blf[o + 1]);
                        mma_bf16(acc[mt][nt], alf[mt], bhf[o], bhf[o + 1]);
                    }
                }
            }
        }
        __syncthreads();
        if (c + 2 < kIters) issue(c + 2, c & 1);
    }

    const int rr  = lane >> 2;
    const int cp2 = (lane & 3) * 2;
    float* Cfb = Cf + offC;
#pragma unroll
    for (int mt = 0; mt < 2; mt++) {
        int row0 = m0 + wm * 32 + mt * 16 + rr;
        int row1 = row0 + 8;
#pragma unroll
        for (int nt = 0; nt < 8; nt++) {
            int col = n0 + wn * 64 + nt * 8 + cp2;
            *(float2*)&Cfb[(size_t)row0 * ldc + col] =
                make_float2(acc[mt][nt][0] * scale, acc[mt][nt][1] * scale);
            *(float2*)&Cfb[(size_t)row1 * ldc + col] =
                make_float2(acc[mt][nt][2] * scale, acc[mt][nt][3] * scale);
        }
    }
}

// ---------------------------------------------------------------------------
// QKV projection GEMM (split bf16 out). sel = selBase + (bx>>2) in {0=Q,1=K,2=V}.
// ---------------------------------------------------------------------------
__global__ __launch_bounds__(256, 2) void gemm_qkv(
    const __nv_bfloat16* __restrict__ xh, const __nv_bfloat16* __restrict__ xl,
    const __nv_bfloat16* __restrict__ wqh, const __nv_bfloat16* __restrict__ wql,
    const __nv_bfloat16* __restrict__ wkh, const __nv_bfloat16* __restrict__ wkl,
    const __nv_bfloat16* __restrict__ wvh, const __nv_bfloat16* __restrict__ wvl,
    __nv_bfloat16* __restrict__ qh, __nv_bfloat16* __restrict__ ql,
    __nv_bfloat16* __restrict__ kh, __nv_bfloat16* __restrict__ kl,
    __nv_bfloat16* __restrict__ vh, __nv_bfloat16* __restrict__ vl,
    float qscale, int selBase)
{
    extern __shared__ char smem[];
    const uint32_t sb0 = smem_u32(smem);
    const int tid  = threadIdx.x;
    const int lane = tid & 31;
    const int wid  = tid >> 5;
    const int wm   = wid >> 1;
    const int wn   = wid & 1;
    const int sel  = selBase + (blockIdx.x >> 2);
    const int n0   = (blockIdx.x & 3) * 128;
    const int m0   = blockIdx.y * 128;

    const __nv_bfloat16* Bhi = sel == 0 ? wqh : sel == 1 ? wkh : wvh;
    const __nv_bfloat16* Blo = sel == 0 ? wql : sel == 1 ? wkl : wvl;
    __nv_bfloat16* Chi = sel == 0 ? qh : sel == 1 ? kh : vh;
    __nv_bfloat16* Clo = sel == 0 ? ql : sel == 1 ? kl : vl;
    const float scale = sel == 0 ? qscale : 1.0f;

    const __nv_bfloat16* aH = xh  + (size_t)m0 * 512;
    const __nv_bfloat16* aL = xl  + (size_t)m0 * 512;
    const __nv_bfloat16* bH = Bhi + (size_t)n0 * 512;
    const __nv_bfloat16* bL = Blo + (size_t)n0 * 512;

    auto issue = [&](int c, int stg) {
        const uint32_t sb = sb0 + stg * STG_BYTES;
        const int k0 = c * 32;
#pragma unroll
        for (int i = 0; i < 2; i++) {
            int o  = tid + i * 256;
            int r  = o >> 2;
            int ch = o & 3;
            uint32_t d = sb + r * 80 + ch * 16;
            const __nv_bfloat16* s;
            s = aH + (size_t)r * 512 + k0 + ch * 8; CP_ASYNC(d,            s);
            s = aL + (size_t)r * 512 + k0 + ch * 8; CP_ASYNC(d + TILE_P,   s);
            s = bH + (size_t)r * 512 + k0 + ch * 8; CP_ASYNC(d + 2*TILE_P, s);
            s = bL + (size_t)r * 512 + k0 + ch * 8; CP_ASYNC(d + 3*TILE_P, s);
        }
        CP_COMMIT();
    };

    issue(0, 0);
    issue(1, 1);

    float acc[2][8][4];
#pragma unroll
    for (int mt = 0; mt < 2; mt++)
#pragma unroll
        for (int nt = 0; nt < 8; nt++)
#pragma unroll
            for (int e = 0; e < 4; e++) acc[mt][nt][e] = 0.f;

    for (int c = 0; c < 16; c++) {
        CP_WAIT1();
        __syncthreads();

        const uint32_t sb = sb0 + (c & 1) * STG_BYTES;
#pragma unroll
        for (int s = 0; s < 2; s++) {
            uint32_t ahf[2][4], alf[2][4];
#pragma unroll
            for (int mt = 0; mt < 2; mt++) {
                uint32_t addr = sb + (uint32_t)((wm * 32 + mt * 16 + (lane & 15)) * 80)
                                   + (uint32_t)((s * 2 + (lane >> 4)) << 4);
                ldsm4(addr,          ahf[mt]);
                ldsm4(addr + TILE_P, alf[mt]);
            }
#pragma unroll
            for (int ng = 0; ng < 4; ng++) {
                int row = wn * 64 + ng * 16 + ((lane >> 4) << 3) + (lane & 7);
                uint32_t addr = sb + 2 * TILE_P + (uint32_t)(row * 80)
                                   + (uint32_t)((s * 2 + ((lane >> 3) & 1)) << 4);
                uint32_t bhf[4], blf[4];
                ldsm4(addr,          bhf);
                ldsm4(addr + TILE_P, blf);
#pragma unroll
                for (int hf = 0; hf < 2; hf++) {
                    int nt = ng * 2 + hf, o = hf * 2;
#pragma unroll
                    for (int mt = 0; mt < 2; mt++) {
                        mma_bf16(acc[mt][nt], ahf[mt], bhf[o], bhf[o + 1]);
                        mma_bf16(acc[mt][nt], ahf[mt], blf[o], blf[o + 1]);
                        mma_bf16(acc[mt][nt], alf[mt], bhf[o], bhf[o + 1]);
                    }
                }
            }
        }
        __syncthreads();
        if (c + 2 < 16) issue(c + 2, c & 1);
    }

    const int rr  = lane >> 2;
    const int cp2 = (lane & 3) * 2;
#pragma unroll
    for (int mt = 0; mt < 2; mt++) {
        int row0 = m0 + wm * 32 + mt * 16 + rr;
        int row1 = row0 + 8;
#pragma unroll
        for (int nt = 0; nt < 8; nt++) {
            int col = n0 + wn * 64 + nt * 8 + cp2;
            __nv_bfloat16 h0, l0, h1, l1;
            bsplit(acc[mt][nt][0] * scale, h0, l0); bsplit(acc[mt][nt][1] * scale, h1, l1);
            *(__nv_bfloat162*)&Chi[(size_t)row0 * 512 + col] = __nv_bfloat162(h0, h1);
            *(__nv_bfloat162*)&Clo[(size_t)row0 * 512 + col] = __nv_bfloat162(l0, l1);
            bsplit(acc[mt][nt][2] * scale, h0, l0); bsplit(acc[mt][nt][3] * scale, h1, l1);
            *(__nv_bfloat162*)&Chi[(size_t)row1 * 512 + col] = __nv_bfloat162(h0, h1);
            *(__nv_bfloat162*)&Clo[(size_t)row1 * 512 + col] = __nv_bfloat162(l0, l1);
        }
    }
}

// ---------------------------------------------------------------------------
// Fused flash attention (R11 schedule; RH 32-col window, pitch 34).
// smem: Q 69632 | K 34816 | V 34816 | RH 17408 = 156672 B.
// ---------------------------------------------------------------------------
#define FL_QH 0
#define FL_QL 34816
#define FL_KH 69632
#define FL_KL 87040
#define FL_VH 104448
#define FL_VL 121856
#define FL_RH 139264
#define FLASH_SMEM (139264 + 17408)

__global__ __launch_bounds__(256) void flash(
    const __nv_bfloat16* __restrict__ qh, const __nv_bfloat16* __restrict__ ql,
    const __nv_bfloat16* __restrict__ kh, const __nv_bfloat16* __restrict__ kl,
    const __nv_bfloat16* __restrict__ vh, const __nv_bfloat16* __restrict__ vl,
    const float* __restrict__ rwh,
    __nv_bfloat16* __restrict__ aoh, __nv_bfloat16* __restrict__ aol)
{
    extern __shared__ char smem[];
    const uint32_t sb = smem_u32(smem);
    float* rhS = (float*)(smem + FL_RH);

    const int tid  = threadIdx.x;
    const int lane = tid & 31;
    const int w    = tid >> 5;
    const int z    = blockIdx.z;
    const int b    = z >> 2;
    const int hh   = z & 3;
    const int qbase = blockIdx.x * 128;

    auto loadK = [&](int it) {
        const int kb = it * 64;
#pragma unroll
        for (int t = 0; t < 4; t++) {
            int idx = tid + t * 256;
            int r = idx >> 4, c = idx & 15;
            size_t g = (size_t)((b << 10) + kb + r) * 512 + hh * 128 + c * 8;
            CP_ASYNC(sb + FL_KH + r * 272 + c * 16, kh + g);
            CP_ASYNC(sb + FL_KL + r * 272 + c * 16, kl + g);
        }
        CP_COMMIT();
    };
    auto loadV = [&](int it) {
        const int kb = it * 64;
#pragma unroll
        for (int t = 0; t < 4; t++) {
            int idx = tid + t * 256;
            int r = idx >> 4, c = idx & 15;
            size_t g = (size_t)((b << 10) + kb + r) * 512 + hh * 128 + c * 8;
            CP_ASYNC(sb + FL_VH + r * 272 + c * 16, vh + g);
            CP_ASYNC(sb + FL_VL + r * 272 + c * 16, vl + g);
        }
        CP_COMMIT();
    };

#pragma unroll
    for (int t = 0; t < 8; t++) {
        int idx = tid + t * 256;
        int r = idx >> 4, c = idx & 15;
        size_t g = (size_t)((b << 10) + qbase + r) * 512 + hh * 128 + c * 8;
        CP_ASYNC(sb + FL_QH + r * 272 + c * 16, qh + g);
        CP_ASYNC(sb + FL_QL + r * 272 + c * 16, ql + g);
    }
    CP_COMMIT();
    loadK(0);
    loadV(0);

    {
        const float* bsrc = rwh + ((size_t)z * 1024 + qbase) * 128;
        for (int i = tid; i < 128 * 32; i += 256) {
            int r = i >> 5, j = i & 31;
            int yq = (qbase + r) >> 5;
            rhS[r * 34 + j] = bsrc[(size_t)r * 128 + 64 + j + 31 - yq];
        }
    }

    const int cp  = (lane & 3) * 2;
    const int r0 = w * 16 + (lane >> 2);
    const int r1 = r0 + 8;
    const int lq0 = qbase + r0, lq1 = qbase + r1;
    const int xq0 = lq0 & 31;
    const int xq1 = lq1 & 31;
    const float L2E = 1.4426950408889634f;

    float rw0[8], rw1[8];
    {
        const float* brow0 = rwh + ((size_t)z * 1024 + lq0) * 128;
        const float* brow1 = rwh + ((size_t)z * 1024 + lq1) * 128;
#pragma unroll
        for (int i = 0; i < 4; i++)
#pragma unroll
            for (int e = 0; e < 2; e++) {
                rw0[i * 2 + e] = brow0[8 * i + cp + e - xq0 + 31];
                rw1[i * 2 + e] = brow1[8 * i + cp + e - xq1 + 31];
            }
    }

    float m0 = -1e30f, m1 = -1e30f, l0 = 0.f, l1 = 0.f;
    float O[16][4];
#pragma unroll
    for (int d = 0; d < 16; d++)
#pragma unroll
        for (int e = 0; e < 4; e++) O[d][e] = 0.f;

    for (int it = 0; it < 16; it++) {
        CP_WAIT1();
        __syncthreads();

        float s[8][4];
#pragma unroll
        for (int nt = 0; nt < 8; nt++)
#pragma unroll
            for (int e = 0; e < 4; e++) s[nt][e] = 0.f;

#pragma unroll
        for (int ks = 0; ks < 8; ks++) {
            uint32_t qhf[4], qlf[4];
            uint32_t addrA = sb + FL_QH + (uint32_t)((w * 16 + (lane & 15)) * 272)
                               + (uint32_t)(ks * 32 + (lane >> 4) * 16);
            ldsm4(addrA,                   qhf);
            ldsm4(addrA + (FL_QL - FL_QH), qlf);
            uint32_t bhf[4][4], blf[4][4];
#pragma unroll
            for (int ng = 0; ng < 4; ng++) {
                int row = ng * 16 + ((lane >> 4) << 3) + (lane & 7);
                uint32_t addrB = sb + FL_KH + (uint32_t)(row * 272)
                                   + (uint32_t)(ks * 32 + ((lane >> 3) & 1) * 16);
                ldsm4(addrB,                   bhf[ng]);
                ldsm4(addrB + (FL_KL - FL_KH), blf[ng]);
            }
#pragma unroll
            for (int nt = 0; nt < 8; nt++) {
                int ng = nt >> 1, o = (nt & 1) * 2;
                mma_bf16(s[nt], qhf, bhf[ng][o], bhf[ng][o + 1]);
                mma_bf16(s[nt], qhf, blf[ng][o], blf[ng][o + 1]);
                mma_bf16(s[nt], qlf, bhf[ng][o], bhf[ng][o + 1]);
            }
        }
        __syncthreads();
        if (it < 15) loadK(it + 1);

        const int j = it * 2;
        float rh0a = rhS[r0 * 34 + j];
        float rh0b = rhS[r0 * 34 + j + 1];
        float rh1a = rhS[r1 * 34 + j];
        float rh1b = rhS[r1 * 34 + j + 1];

        float mx0 = m0, mx1 = m1;
#pragma unroll
        for (int nt = 0; nt < 8; nt++) {
            const float rh0 = (nt < 4) ? rh0a : rh0b;
            const float rh1 = (nt < 4) ? rh1a : rh1b;
            const int i2 = (nt & 3) * 2;
            s[nt][0] += rw0[i2]     + rh0;
            s[nt][1] += rw0[i2 + 1] + rh0;
            s[nt][2] += rw1[i2]     + rh1;
            s[nt][3] += rw1[i2 + 1] + rh1;
            mx0 = fmaxf(mx0, fmaxf(s[nt][0], s[nt][1]));
            mx1 = fmaxf(mx1, fmaxf(s[nt][2], s[nt][3]));
        }
        mx0 = fmaxf(mx0, __shfl_xor_sync(0xffffffffu, mx0, 1));
        mx0 = fmaxf(mx0, __shfl_xor_sync(0xffffffffu, mx0, 2));
        mx1 = fmaxf(mx1, __shfl_xor_sync(0xffffffffu, mx1, 1));
        mx1 = fmaxf(mx1, __shfl_xor_sync(0xffffffffu, mx1, 2));

        float a0 = exp2f((m0 - mx0) * L2E);
        float a1 = exp2f((m1 - mx1) * L2E);
        m0 = mx0; m1 = mx1;

        float s0 = 0.f, s1 = 0.f;
#pragma unroll
        for (int nt = 0; nt < 8; nt++) {
            s[nt][0] = exp2f((s[nt][0] - m0) * L2E);
            s[nt][1] = exp2f((s[nt][1] - m0) * L2E);
            s[nt][2] = exp2f((s[nt][2] - m1) * L2E);
            s[nt][3] = exp2f((s[nt][3] - m1) * L2E);
            s0 += s[nt][0] + s[nt][1];
            s1 += s[nt][2] + s[nt][3];
        }
        s0 += __shfl_xor_sync(0xffffffffu, s0, 1);
        s0 += __shfl_xor_sync(0xffffffffu, s0, 2);
        s1 += __shfl_xor_sync(0xffffffffu, s1, 1);
        s1 += __shfl_xor_sync(0xffffffffu, s1, 2);
        l0 = l0 * a0 + s0;
        l1 = l1 * a1 + s1;

#pragma unroll
        for (int d = 0; d < 16; d++) {
            O[d][0] *= a0; O[d][1] *= a0;
            O[d][2] *= a1; O[d][3] *= a1;
        }

        if (it < 15) { CP_WAIT1(); } else { CP_WAIT0(); }
        __syncthreads();

#pragma unroll
        for (int ks = 0; ks < 4; ks++) {
            uint32_t pah[4], pal[4];
            {
                __nv_bfloat16 h00,l00,h01,l01,h02,l02,h03,l03;
                __nv_bfloat16 h10,l10,h11,l11,h12,l12,h13,l13;
                bsplit(s[2*ks][0],   h00, l00); bsplit(s[2*ks][1],   h01, l01);
                bsplit(s[2*ks][2],   h02, l02); bsplit(s[2*ks][3],   h03, l03);
                bsplit(s[2*ks+1][0], h10, l10); bsplit(s[2*ks+1][1], h11, l11);
                bsplit(s[2*ks+1][2], h12, l12); bsplit(s[2*ks+1][3], h13, l13);
                pah[0] = packbf(h00, h01); pah[1] = packbf(h02, h03);
                pah[2] = packbf(h10, h11); pah[3] = packbf(h12, h13);
                pal[0] = packbf(l00, l01); pal[1] = packbf(l02, l03);
                pal[2] = packbf(l10, l11); pal[3] = packbf(l12, l13);
            }
            uint32_t vrow = (uint32_t)(ks * 16 + (lane & 7) + (((lane >> 3) & 1) << 3));
            uint32_t vcb  = (uint32_t)((lane >> 4) << 4);
#pragma unroll
            for (int dg = 0; dg < 8; dg++) {
                uint32_t addrV = sb + FL_VH + vrow * 272 + (uint32_t)(dg * 32) + vcb;
                uint32_t vhf[4], vlf[4];
                ldsm4t(addrV,                   vhf);
                ldsm4t(addrV + (FL_VL - FL_VH), vlf);
#pragma unroll
                for (int hf = 0; hf < 2; hf++) {
                    int dnt = dg * 2 + hf, o = hf * 2;
                    mma_bf16(O[dnt], pah, vhf[o], vhf[o + 1]);
                    mma_bf16(O[dnt], pah, vlf[o], vlf[o + 1]);
                    mma_bf16(O[dnt], pal, vhf[o], vhf[o + 1]);
                }
            }
        }
        __syncthreads();
        if (it < 15) loadV(it + 1);
    }

    float inv0 = 1.0f / l0, inv1 = 1.0f / l1;
    size_t row0g = (size_t)((b << 10) + lq0) * 512 + hh * 128;
    size_t row1g = (size_t)((b << 10) + lq1) * 512 + hh * 128;
#pragma unroll
    for (int d = 0; d < 16; d++) {
        int col = d * 8 + cp;
        __nv_bfloat16 h0, lo0, h1, lo1;
        bsplit(O[d][0] * inv0, h0, lo0); bsplit(O[d][1] * inv0, h1, lo1);
        *(__nv_bfloat162*)&aoh[row0g + col] = __nv_bfloat162(h0, h1);
        *(__nv_bfloat162*)&aol[row0g + col] = __nv_bfloat162(lo0, lo1);
        bsplit(O[d][2] * inv1, h0, lo0); bsplit(O[d][3] * inv1, h1, lo1);
        *(__nv_bfloat162*)&aoh[row1g + col] = __nv_bfloat162(h0, h1);
        *(__nv_bfloat162*)&aol[row1g + col] = __nv_bfloat162(lo0, lo1);
    }
}

// ---------------------------------------------------------------------------
// x -> bf16 hi/lo split
// ---------------------------------------------------------------------------
__global__ __launch_bounds__(256) void splitx(const float* __restrict__ x,
                                              __nv_bfloat16* __restrict__ xh,
                                              __nv_bfloat16* __restrict__ xl, int n4)
{
    for (int i = blockIdx.x * 256 + threadIdx.x; i < n4; i += gridDim.x * 256) {
        float4 v = ((const float4*)x)[i];
        __nv_bfloat16 h0,l0,h1,l1,h2,l2,h3,l3;
        bsplit(v.x,h0,l0); bsplit(v.y,h1,l1); bsplit(v.z,h2,l2); bsplit(v.w,h3,l3);
        ((__nv_bfloat162*)xh)[i*2]   = __nv_bfloat162(h0,h1);
        ((__nv_bfloat162*)xh)[i*2+1] = __nv_bfloat162(h2,h3);
        ((__nv_bfloat162*)xl)[i*2]   = __nv_bfloat162(l0,l1);
        ((__nv_bfloat162*)xl)[i*2+1] = __nv_bfloat162(l2,l3);
    }
}

// ---------------------------------------------------------------------------
// Merged weight prep: z<4 -> transpose+split weight z; z==4 -> pos tables.
// ---------------------------------------------------------------------------
__global__ void wprep(const float* __restrict__ Wq, const float* __restrict__ Wk,
                      const float* __restrict__ Wv, const float* __restrict__ Wo,
                      const float* __restrict__ pew, const float* __restrict__ peh,
                      __nv_bfloat16* __restrict__ wqh, __nv_bfloat16* __restrict__ wql,
                      __nv_bfloat16* __restrict__ wkh, __nv_bfloat16* __restrict__ wkl,
                      __nv_bfloat16* __restrict__ wvh, __nv_bfloat16* __restrict__ wvl,
                      __nv_bfloat16* __restrict__ woh, __nv_bfloat16* __restrict__ wol,
                      __nv_bfloat16* __restrict__ pbh, __nv_bfloat16* __restrict__ pbl)
{
    const int zz = blockIdx.z;
    if (zz < 4) {
        const float* W = zz == 0 ? Wq : zz == 1 ? Wk : zz == 2 ? Wv : Wo;
        __nv_bfloat16* th = zz == 0 ? wqh : zz == 1 ? wkh : zz == 2 ? wvh : woh;
        __nv_bfloat16* tl = zz == 0 ? wql : zz == 1 ? wkl : zz == 2 ? wvl : wol;
        __shared__ float t[32][33];
        int x = blockIdx.x * 32 + threadIdx.x;
        int y = blockIdx.y * 32 + threadIdx.y;
#pragma unroll
        for (int j = 0; j < 32; j += 8)
            t[threadIdx.y + j][threadIdx.x] = W[(size_t)(y + j) * 512 + x];
        __syncthreads();
        int x2 = blockIdx.y * 32 + threadIdx.x;
        int y2 = blockIdx.x * 32 + threadIdx.y;
#pragma unroll
        for (int j = 0; j < 32; j += 8) {
            float val = t[threadIdx.x][threadIdx.y + j];
            __nv_bfloat16 h, l;
            bsplit(val, h, l);
            size_t o = (size_t)(y2 + j) * 512 + x2;
            th[o] = h; tl[o] = l;
        }
    } else {
        int blk = blockIdx.y * 16 + blockIdx.x;
        if (blk >= 64) return;
        int i = blk * 256 + threadIdx.y * 32 + threadIdx.x;
        int n = i >> 7, k = i & 127;
        float v = 0.f;
        if (n < NREL)                 v = pew[k * NREL + n];
        else if (n >= 64 && n < 127)  v = peh[k * NREL + (n - 64)];
        __nv_bfloat16 h, l;
        bsplit(v, h, l);
        pbh[i] = h; pbl[i] = l;
    }
}

// ---------------------------------------------------------------------------
extern "C" void kernel_launch(void* const* d_in, const int* in_sizes, int n_in,
                              void* d_out, int out_size)
{
    const float* x   = (const float*)d_in[0];
    const float* Wq  = (const float*)d_in[1];
    const float* Wk  = (const float*)d_in[2];
    const float* Wv  = (const float*)d_in[3];
    const float* Wo  = (const float*)d_in[4];
    const float* pew = (const float*)d_in[5];
    const float* peh = (const float*)d_in[6];
    float* out = (float*)d_out;

    float* rwhp;
    __nv_bfloat16 *xh,*xl,*qh,*ql,*kh,*kl,*vh,*vl,*aoh,*aol,*pbh,*pbl;
    __nv_bfloat16 *wqh,*wql,*wkh,*wkl,*wvh,*wvl,*woh,*wol;
    cudaGetSymbolAddress((void**)&rwhp, g_rwh);
    cudaGetSymbolAddress((void**)&xh,  g_xh);  cudaGetSymbolAddress((void**)&xl,  g_xl);
    cudaGetSymbolAddress((void**)&qh,  g_qh);  cudaGetSymbolAddress((void**)&ql,  g_ql);
    cudaGetSymbolAddress((void**)&kh,  g_kh);  cudaGetSymbolAddress((void**)&kl,  g_kl);
    cudaGetSymbolAddress((void**)&vh,  g_vh);  cudaGetSymbolAddress((void**)&vl,  g_vl);
    cudaGetSymbolAddress((void**)&aoh, g_aoh); cudaGetSymbolAddress((void**)&aol, g_aol);
    cudaGetSymbolAddress((void**)&pbh, g_pbh); cudaGetSymbolAddress((void**)&pbl, g_pbl);
    cudaGetSymbolAddress((void**)&wqh, g_wqh); cudaGetSymbolAddress((void**)&wql, g_wql);
    cudaGetSymbolAddress((void**)&wkh, g_wkh); cudaGetSymbolAddress((void**)&wkl, g_wkl);
    cudaGetSymbolAddress((void**)&wvh, g_wvh); cudaGetSymbolAddress((void**)&wvl, g_wvl);
    cudaGetSymbolAddress((void**)&woh, g_woh); cudaGetSymbolAddress((void**)&wol, g_wol);

    cudaFuncSetAttribute(gemm_bs,  cudaFuncAttributeMaxDynamicSharedMemorySize, GEMM_SMEM);
    cudaFuncSetAttribute(gemm_qkv, cudaFuncAttributeMaxDynamicSharedMemorySize, GEMM_SMEM);
    cudaFuncSetAttribute(flash,    cudaFuncAttributeMaxDynamicSharedMemorySize, FLASH_SMEM);

    const float scale = 0.08838834764831845f;   // 1/sqrt(128)

    // Try forked-stream schedule; fall back to serial on failure.
    cudaStream_t s1 = nullptr;
    cudaEvent_t e0 = nullptr, eX = nullptr, eW = nullptr, eKV = nullptr;
    bool forked =
        cudaStreamCreateWithFlags(&s1, cudaStreamNonBlocking) == cudaSuccess &&
        cudaEventCreateWithFlags(&e0,  cudaEventDisableTiming) == cudaSuccess &&
        cudaEventCreateWithFlags(&eX,  cudaEventDisableTiming) == cudaSuccess &&
        cudaEventCreateWithFlags(&eW,  cudaEventDisableTiming) == cudaSuccess &&
        cudaEventCreateWithFlags(&eKV, cudaEventDisableTiming) == cudaSuccess;

    if (forked) {
        // fork s1 from the capture-origin (legacy) stream
        cudaEventRecord(e0, 0);
        cudaStreamWaitEvent(s1, e0, 0);

        // s1: weight prep            s0: input split   (concurrent)
        wprep<<<dim3(16, 16, 5), dim3(32, 8), 0, s1>>>(Wq, Wk, Wv, Wo, pew, peh,
            wqh, wql, wkh, wkl, wvh, wvl, woh, wol, pbh, pbl);
        cudaEventRecord(eW, s1);
        splitx<<<1024, 256>>>(x, xh, xl, 8192*512/4);
        cudaEventRecord(eX, 0);

        // s0: Q projection (needs x + Wq)
        cudaStreamWaitEvent(0, eW, 0);
        gemm_qkv<<<dim3(4, 64), 256, GEMM_SMEM>>>(xh, xl,
            wqh, wql, wkh, wkl, wvh, wvl, qh, ql, kh, kl, vh, vl, scale, 0);
        // s1: K,V projections (needs x + Wk/Wv), concurrent with relpos below
        cudaStreamWaitEvent(s1, eX, 0);
        gemm_qkv<<<dim3(8, 64), 256, GEMM_SMEM, s1>>>(xh, xl,
            wqh, wql, wkh, wkl, wvh, wvl, qh, ql, kh, kl, vh, vl, scale, 1);
        cudaEventRecord(eKV, s1);

        // s0: relpos GEMM (needs q + pos tables)
        gemm_bs<<<dim3(1, 8, 32), 256, GEMM_SMEM>>>(
            qh, ql, 512, 524288LL, 128LL,
            pbh, pbl, 128, 0, 0,
            rwhp, 128, 524288LL, 131072LL,
            4, 1.0f);

        // join: flash needs K/V too
        cudaStreamWaitEvent(0, eKV, 0);
        flash<<<dim3(8, 1, 32), 256, FLASH_SMEM>>>(qh, ql, kh, kl, vh, vl, rwhp, aoh, aol);
        gemm_bs<<<dim3(4, 64, 1), 256, GEMM_SMEM>>>(
            aoh, aol, 512, 0, 0, woh, wol, 512, 0, 0,
            out, 512, 0, 0, 16, 1.0f);
    } else {
        splitx<<<1024, 256>>>(x, xh, xl, 8192*512/4);
        wprep<<<dim3(16, 16, 5), dim3(32, 8)>>>(Wq, Wk, Wv, Wo, pew, peh,
            wqh, wql, wkh, wkl, wvh, wvl, woh, wol, pbh, pbl);
        gemm_qkv<<<dim3(12, 64), 256, GEMM_SMEM>>>(xh, xl,
            wqh, wql, wkh, wkl, wvh, wvl, qh, ql, kh, kl, vh, vl, scale, 0);
        gemm_bs<<<dim3(1, 8, 32), 256, GEMM_SMEM>>>(
            qh, ql, 512, 524288LL, 128LL,
            pbh, pbl, 128, 0, 0,
            rwhp, 128, 524288LL, 131072LL,
            4, 1.0f);
        flash<<<dim3(8, 1, 32), 256, FLASH_SMEM>>>(qh, ql, kh, kl, vh, vl, rwhp, aoh, aol);
        gemm_bs<<<dim3(4, 64, 1), 256, GEMM_SMEM>>>(
            aoh, aol, 512, 0, 0, woh, wol, 512, 0, 0,
            out, 512, 0, 0, 16, 1.0f);
    }
}

// round 16
// speedup vs baseline: 1.0339x; 1.0339x over previous
#include <cuda_runtime.h>
#include <cuda_bf16.h>
#include <cstdint>

// Problem constants
#define BB     8
#define LL     1024
#define HEADS  4
#define KD     128
#define EMB    512
#define NREL   63

// ---------------------------------------------------------------------------
// Device-global scratch (no allocations allowed)
// ---------------------------------------------------------------------------
__device__ float          g_rwh[32*1024*128];        // fused RW|RH bias, pitch 128
__device__ __nv_bfloat16  g_xh [BB*LL*EMB], g_xl [BB*LL*EMB];
__device__ __nv_bfloat16  g_qh [BB*LL*EMB], g_ql [BB*LL*EMB];
__device__ __nv_bfloat16  g_kh [BB*LL*EMB], g_kl [BB*LL*EMB];
__device__ __nv_bfloat16  g_vh [BB*LL*EMB], g_vl [BB*LL*EMB];
__device__ __nv_bfloat16  g_aoh[BB*LL*EMB], g_aol[BB*LL*EMB];
__device__ __nv_bfloat16  g_wqh[EMB*EMB], g_wql[EMB*EMB];
__device__ __nv_bfloat16  g_wkh[EMB*EMB], g_wkl[EMB*EMB];
__device__ __nv_bfloat16  g_wvh[EMB*EMB], g_wvl[EMB*EMB];
__device__ __nv_bfloat16  g_woh[EMB*EMB], g_wol[EMB*EMB];
__device__ __nv_bfloat16  g_pbh[128*128], g_pbl[128*128];   // padded [posW|posH]^T

// ---------------------------------------------------------------------------
// PTX helpers
// ---------------------------------------------------------------------------
__device__ __forceinline__ uint32_t smem_u32(const void* p) {
    uint32_t a;
    asm("{ .reg .u64 t; cvta.to.shared.u64 t, %1; cvt.u32.u64 %0, t; }" : "=r"(a) : "l"(p));
    return a;
}
__device__ __forceinline__ void ldsm4(uint32_t addr, uint32_t* r) {
    asm volatile("ldmatrix.sync.aligned.m8n8.x4.shared.b16 {%0,%1,%2,%3}, [%4];"
                 : "=r"(r[0]), "=r"(r[1]), "=r"(r[2]), "=r"(r[3]) : "r"(addr));
}
__device__ __forceinline__ void ldsm4t(uint32_t addr, uint32_t* r) {
    asm volatile("ldmatrix.sync.aligned.m8n8.x4.trans.shared.b16 {%0,%1,%2,%3}, [%4];"
                 : "=r"(r[0]), "=r"(r[1]), "=r"(r[2]), "=r"(r[3]) : "r"(addr));
}
__device__ __forceinline__ void mma_bf16(float* d, const uint32_t* a, uint32_t b0, uint32_t b1) {
    asm volatile("mma.sync.aligned.m16n8k16.row.col.f32.bf16.bf16.f32 "
                 "{%0,%1,%2,%3}, {%4,%5,%6,%7}, {%8,%9}, {%0,%1,%2,%3};"
                 : "+f"(d[0]), "+f"(d[1]), "+f"(d[2]), "+f"(d[3])
                 : "r"(a[0]), "r"(a[1]), "r"(a[2]), "r"(a[3]), "r"(b0), "r"(b1));
}
#define CP_ASYNC(dst, src) asm volatile("cp.async.ca.shared.global [%0], [%1], 16;" :: "r"(dst), "l"(src))
#define CP_COMMIT()        asm volatile("cp.async.commit_group;" ::: "memory")
#define CP_WAIT1()         asm volatile("cp.async.wait_group 1;" ::: "memory")
#define CP_WAIT0()         asm volatile("cp.async.wait_group 0;" ::: "memory")

__device__ __forceinline__ void bsplit(float x, __nv_bfloat16& h, __nv_bfloat16& l) {
    h = __float2bfloat16_rn(x);
    l = __float2bfloat16_rn(x - __bfloat162float(h));
}
__device__ __forceinline__ uint32_t packbf(__nv_bfloat16 a, __nv_bfloat16 b) {
    __nv_bfloat162 t(a, b);
    return *(uint32_t*)&t;
}

// ---------------------------------------------------------------------------
// GEMM machinery: 128x128 CTA tile, BK=32, 2-stage, 128 threads (4 warps),
// warp tile 64m x 64n -> 6 mma per ldsm.x4 (3x smem-read efficiency).
// ---------------------------------------------------------------------------
#define STG_BYTES 40960
#define TILE_P    10240
#define GEMM_SMEM (2 * STG_BYTES)

// ---------------------------------------------------------------------------
// bf16-split pipelined mma GEMM (generic, fp32 out): C = (A@B^T)*scale
// ---------------------------------------------------------------------------
__global__ __launch_bounds__(128, 2) void gemm_bs(
    const __nv_bfloat16* __restrict__ Ahi, const __nv_bfloat16* __restrict__ Alo,
    int lda, long long strA1, long long strA2,
    const __nv_bfloat16* __restrict__ Bhi, const __nv_bfloat16* __restrict__ Blo,
    int ldb, long long strB1, long long strB2,
    float* __restrict__ Cf,
    int ldc, long long strC1, long long strC2,
    int kIters, float scale)
{
    extern __shared__ char smem[];
    const uint32_t sb0 = smem_u32(smem);
    const int tid  = threadIdx.x;
    const int lane = tid & 31;
    const int wid  = tid >> 5;
    const int wm   = wid >> 1;          // 0..1 -> 64-row half
    const int wn   = wid & 1;           // 0..1 -> 64-col half
    const int n0   = blockIdx.x * 128;
    const int m0   = blockIdx.y * 128;
    const int z    = blockIdx.z;

    const size_t offA = (size_t)(z >> 2) * strA1 + (size_t)(z & 3) * strA2;
    const size_t offB = (size_t)(z >> 2) * strB1 + (size_t)(z & 3) * strB2;
    const size_t offC = (size_t)(z >> 2) * strC1 + (size_t)(z & 3) * strC2;

    const __nv_bfloat16* aH = Ahi + offA + (size_t)m0 * lda;
    const __nv_bfloat16* aL = Alo + offA + (size_t)m0 * lda;
    const __nv_bfloat16* bH = Bhi + offB + (size_t)n0 * ldb;
    const __nv_bfloat16* bL = Blo + offB + (size_t)n0 * ldb;

    auto issue = [&](int c, int stg) {
        const uint32_t sb = sb0 + stg * STG_BYTES;
        const int k0 = c * 32;
#pragma unroll
        for (int i = 0; i < 4; i++) {
            int o  = tid + i * 128;
            int r  = o >> 2;
            int ch = o & 3;
            uint32_t d = sb + r * 80 + ch * 16;
            const __nv_bfloat16* s;
            s = aH + (size_t)r * lda + k0 + ch * 8; CP_ASYNC(d,            s);
            s = aL + (size_t)r * lda + k0 + ch * 8; CP_ASYNC(d + TILE_P,   s);
            s = bH + (size_t)r * ldb + k0 + ch * 8; CP_ASYNC(d + 2*TILE_P, s);
            s = bL + (size_t)r * ldb + k0 + ch * 8; CP_ASYNC(d + 3*TILE_P, s);
        }
        CP_COMMIT();
    };

    issue(0, 0);
    if (kIters > 1) issue(1, 1);

    float acc[4][8][4];
#pragma unroll
    for (int mt = 0; mt < 4; mt++)
#pragma unroll
        for (int nt = 0; nt < 8; nt++)
#pragma unroll
            for (int e = 0; e < 4; e++) acc[mt][nt][e] = 0.f;

    for (int c = 0; c < kIters; c++) {
        CP_WAIT1();
        __syncthreads();

        const uint32_t sb = sb0 + (c & 1) * STG_BYTES;
#pragma unroll
        for (int s = 0; s < 2; s++) {
            uint32_t ahf[4][4], alf[4][4];
#pragma unroll
            for (int mt = 0; mt < 4; mt++) {
                uint32_t addr = sb + (uint32_t)((wm * 64 + mt * 16 + (lane & 15)) * 80)
                                   + (uint32_t)((s * 2 + (lane >> 4)) << 4);
                ldsm4(addr,          ahf[mt]);
                ldsm4(addr + TILE_P, alf[mt]);
            }
#pragma unroll
            for (int ng = 0; ng < 4; ng++) {
                int row = wn * 64 + ng * 16 + ((lane >> 4) << 3) + (lane & 7);
                uint32_t addr = sb + 2 * TILE_P + (uint32_t)(row * 80)
                                   + (uint32_t)((s * 2 + ((lane >> 3) & 1)) << 4);
                uint32_t bhf[4], blf[4];
                ldsm4(addr,          bhf);
                ldsm4(addr + TILE_P, blf);
#pragma unroll
                for (int hf = 0; hf < 2; hf++) {
                    int nt = ng * 2 + hf, o = hf * 2;
#pragma unroll
                    for (int mt = 0; mt < 4; mt++) {
                        mma_bf16(acc[mt][nt], ahf[mt], bhf[o], bhf[o + 1]);
                        mma_bf16(acc[mt][nt], ahf[mt], blf[o], blf[o + 1]);
                        mma_bf16(acc[mt][nt], alf[mt], bhf[o], bhf[o + 1]);
                    }
                }
            }
        }
        __syncthreads();
        if (c + 2 < kIters) issue(c + 2, c & 1);
    }

    const int rr  = lane >> 2;
    const int cp2 = (lane & 3) * 2;
    float* Cfb = Cf + offC;
#pragma unroll
    for (int mt = 0; mt < 4; mt++) {
        int row0 = m0 + wm * 64 + mt * 16 + rr;
        int row1 = row0 + 8;
#pragma unroll
        for (int nt = 0; nt < 8; nt++) {
            int col = n0 + wn * 64 + nt * 8 + cp2;
            *(float2*)&Cfb[(size_t)row0 * ldc + col] =
                make_float2(acc[mt][nt][0] * scale, acc[mt][nt][1] * scale);
            *(float2*)&Cfb[(size_t)row1 * ldc + col] =
                make_float2(acc[mt][nt][2] * scale, acc[mt][nt][3] * scale);
        }
    }
}

// ---------------------------------------------------------------------------
// Fused QKV projection GEMM (split bf16 out). grid (12, 64), 128 threads.
// ---------------------------------------------------------------------------
__global__ __launch_bounds__(128, 2) void gemm_qkv(
    const __nv_bfloat16* __restrict__ xh, const __nv_bfloat16* __restrict__ xl,
    const __nv_bfloat16* __restrict__ wqh, const __nv_bfloat16* __restrict__ wql,
    const __nv_bfloat16* __restrict__ wkh, const __nv_bfloat16* __restrict__ wkl,
    const __nv_bfloat16* __restrict__ wvh, const __nv_bfloat16* __restrict__ wvl,
    __nv_bfloat16* __restrict__ qh, __nv_bfloat16* __restrict__ ql,
    __nv_bfloat16* __restrict__ kh, __nv_bfloat16* __restrict__ kl,
    __nv_bfloat16* __restrict__ vh, __nv_bfloat16* __restrict__ vl,
    float qscale)
{
    extern __shared__ char smem[];
    const uint32_t sb0 = smem_u32(smem);
    const int tid  = threadIdx.x;
    const int lane = tid & 31;
    const int wid  = tid >> 5;
    const int wm   = wid >> 1;
    const int wn   = wid & 1;
    const int sel  = blockIdx.x >> 2;
    const int n0   = (blockIdx.x & 3) * 128;
    const int m0   = blockIdx.y * 128;

    const __nv_bfloat16* Bhi = sel == 0 ? wqh : sel == 1 ? wkh : wvh;
    const __nv_bfloat16* Blo = sel == 0 ? wql : sel == 1 ? wkl : wvl;
    __nv_bfloat16* Chi = sel == 0 ? qh : sel == 1 ? kh : vh;
    __nv_bfloat16* Clo = sel == 0 ? ql : sel == 1 ? kl : vl;
    const float scale = sel == 0 ? qscale : 1.0f;

    const __nv_bfloat16* aH = xh  + (size_t)m0 * 512;
    const __nv_bfloat16* aL = xl  + (size_t)m0 * 512;
    const __nv_bfloat16* bH = Bhi + (size_t)n0 * 512;
    const __nv_bfloat16* bL = Blo + (size_t)n0 * 512;

    auto issue = [&](int c, int stg) {
        const uint32_t sb = sb0 + stg * STG_BYTES;
        const int k0 = c * 32;
#pragma unroll
        for (int i = 0; i < 4; i++) {
            int o  = tid + i * 128;
            int r  = o >> 2;
            int ch = o & 3;
            uint32_t d = sb + r * 80 + ch * 16;
            const __nv_bfloat16* s;
            s = aH + (size_t)r * 512 + k0 + ch * 8; CP_ASYNC(d,            s);
            s = aL + (size_t)r * 512 + k0 + ch * 8; CP_ASYNC(d + TILE_P,   s);
            s = bH + (size_t)r * 512 + k0 + ch * 8; CP_ASYNC(d + 2*TILE_P, s);
            s = bL + (size_t)r * 512 + k0 + ch * 8; CP_ASYNC(d + 3*TILE_P, s);
        }
        CP_COMMIT();
    };

    issue(0, 0);
    issue(1, 1);

    float acc[4][8][4];
#pragma unroll
    for (int mt = 0; mt < 4; mt++)
#pragma unroll
        for (int nt = 0; nt < 8; nt++)
#pragma unroll
            for (int e = 0; e < 4; e++) acc[mt][nt][e] = 0.f;

    for (int c = 0; c < 16; c++) {
        CP_WAIT1();
        __syncthreads();

        const uint32_t sb = sb0 + (c & 1) * STG_BYTES;
#pragma unroll
        for (int s = 0; s < 2; s++) {
            uint32_t ahf[4][4], alf[4][4];
#pragma unroll
            for (int mt = 0; mt < 4; mt++) {
                uint32_t addr = sb + (uint32_t)((wm * 64 + mt * 16 + (lane & 15)) * 80)
                                   + (uint32_t)((s * 2 + (lane >> 4)) << 4);
                ldsm4(addr,          ahf[mt]);
                ldsm4(addr + TILE_P, alf[mt]);
            }
#pragma unroll
            for (int ng = 0; ng < 4; ng++) {
                int row = wn * 64 + ng * 16 + ((lane >> 4) << 3) + (lane & 7);
                uint32_t addr = sb + 2 * TILE_P + (uint32_t)(row * 80)
                                   + (uint32_t)((s * 2 + ((lane >> 3) & 1)) << 4);
                uint32_t bhf[4], blf[4];
                ldsm4(addr,          bhf);
                ldsm4(addr + TILE_P, blf);
#pragma unroll
                for (int hf = 0; hf < 2; hf++) {
                    int nt = ng * 2 + hf, o = hf * 2;
#pragma unroll
                    for (int mt = 0; mt < 4; mt++) {
                        mma_bf16(acc[mt][nt], ahf[mt], bhf[o], bhf[o + 1]);
                        mma_bf16(acc[mt][nt], ahf[mt], blf[o], blf[o + 1]);
                        mma_bf16(acc[mt][nt], alf[mt], bhf[o], bhf[o + 1]);
                    }
                }
            }
        }
        __syncthreads();
        if (c + 2 < 16) issue(c + 2, c & 1);
    }

    const int rr  = lane >> 2;
    const int cp2 = (lane & 3) * 2;
#pragma unroll
    for (int mt = 0; mt < 4; mt++) {
        int row0 = m0 + wm * 64 + mt * 16 + rr;
        int row1 = row0 + 8;
#pragma unroll
        for (int nt = 0; nt < 8; nt++) {
            int col = n0 + wn * 64 + nt * 8 + cp2;
            __nv_bfloat16 h0, l0, h1, l1;
            bsplit(acc[mt][nt][0] * scale, h0, l0); bsplit(acc[mt][nt][1] * scale, h1, l1);
            *(__nv_bfloat162*)&Chi[(size_t)row0 * 512 + col] = __nv_bfloat162(h0, h1);
            *(__nv_bfloat162*)&Clo[(size_t)row0 * 512 + col] = __nv_bfloat162(l0, l1);
            bsplit(acc[mt][nt][2] * scale, h0, l0); bsplit(acc[mt][nt][3] * scale, h1, l1);
            *(__nv_bfloat162*)&Chi[(size_t)row1 * 512 + col] = __nv_bfloat162(h0, h1);
            *(__nv_bfloat162*)&Clo[(size_t)row1 * 512 + col] = __nv_bfloat162(l0, l1);
        }
    }
}

// ---------------------------------------------------------------------------
// Fused flash attention (R11 schedule; RH 32-col window, pitch 34). UNCHANGED.
// smem: Q 69632 | K 34816 | V 34816 | RH 17408 = 156672 B.
// ---------------------------------------------------------------------------
#define FL_QH 0
#define FL_QL 34816
#define FL_KH 69632
#define FL_KL 87040
#define FL_VH 104448
#define FL_VL 121856
#define FL_RH 139264
#define FLASH_SMEM (139264 + 17408)

__global__ __launch_bounds__(256) void flash(
    const __nv_bfloat16* __restrict__ qh, const __nv_bfloat16* __restrict__ ql,
    const __nv_bfloat16* __restrict__ kh, const __nv_bfloat16* __restrict__ kl,
    const __nv_bfloat16* __restrict__ vh, const __nv_bfloat16* __restrict__ vl,
    const float* __restrict__ rwh,
    __nv_bfloat16* __restrict__ aoh, __nv_bfloat16* __restrict__ aol)
{
    extern __shared__ char smem[];
    const uint32_t sb = smem_u32(smem);
    float* rhS = (float*)(smem + FL_RH);

    const int tid  = threadIdx.x;
    const int lane = tid & 31;
    const int w    = tid >> 5;
    const int z    = blockIdx.z;
    const int b    = z >> 2;
    const int hh   = z & 3;
    const int qbase = blockIdx.x * 128;

    auto loadK = [&](int it) {
        const int kb = it * 64;
#pragma unroll
        for (int t = 0; t < 4; t++) {
            int idx = tid + t * 256;
            int r = idx >> 4, c = idx & 15;
            size_t g = (size_t)((b << 10) + kb + r) * 512 + hh * 128 + c * 8;
            CP_ASYNC(sb + FL_KH + r * 272 + c * 16, kh + g);
            CP_ASYNC(sb + FL_KL + r * 272 + c * 16, kl + g);
        }
        CP_COMMIT();
    };
    auto loadV = [&](int it) {
        const int kb = it * 64;
#pragma unroll
        for (int t = 0; t < 4; t++) {
            int idx = tid + t * 256;
            int r = idx >> 4, c = idx & 15;
            size_t g = (size_t)((b << 10) + kb + r) * 512 + hh * 128 + c * 8;
            CP_ASYNC(sb + FL_VH + r * 272 + c * 16, vh + g);
            CP_ASYNC(sb + FL_VL + r * 272 + c * 16, vl + g);
        }
        CP_COMMIT();
    };

#pragma unroll
    for (int t = 0; t < 8; t++) {
        int idx = tid + t * 256;
        int r = idx >> 4, c = idx & 15;
        size_t g = (size_t)((b << 10) + qbase + r) * 512 + hh * 128 + c * 8;
        CP_ASYNC(sb + FL_QH + r * 272 + c * 16, qh + g);
        CP_ASYNC(sb + FL_QL + r * 272 + c * 16, ql + g);
    }
    CP_COMMIT();
    loadK(0);
    loadV(0);

    {
        const float* bsrc = rwh + ((size_t)z * 1024 + qbase) * 128;
        for (int i = tid; i < 128 * 32; i += 256) {
            int r = i >> 5, j = i & 31;
            int yq = (qbase + r) >> 5;
            rhS[r * 34 + j] = bsrc[(size_t)r * 128 + 64 + j + 31 - yq];
        }
    }

    const int cp  = (lane & 3) * 2;
    const int r0 = w * 16 + (lane >> 2);
    const int r1 = r0 + 8;
    const int lq0 = qbase + r0, lq1 = qbase + r1;
    const int xq0 = lq0 & 31;
    const int xq1 = lq1 & 31;
    const float L2E = 1.4426950408889634f;

    float rw0[8], rw1[8];
    {
        const float* brow0 = rwh + ((size_t)z * 1024 + lq0) * 128;
        const float* brow1 = rwh + ((size_t)z * 1024 + lq1) * 128;
#pragma unroll
        for (int i = 0; i < 4; i++)
#pragma unroll
            for (int e = 0; e < 2; e++) {
                rw0[i * 2 + e] = brow0[8 * i + cp + e - xq0 + 31];
                rw1[i * 2 + e] = brow1[8 * i + cp + e - xq1 + 31];
            }
    }

    float m0 = -1e30f, m1 = -1e30f, l0 = 0.f, l1 = 0.f;
    float O[16][4];
#pragma unroll
    for (int d = 0; d < 16; d++)
#pragma unroll
        for (int e = 0; e < 4; e++) O[d][e] = 0.f;

    for (int it = 0; it < 16; it++) {
        CP_WAIT1();
        __syncthreads();

        float s[8][4];
#pragma unroll
        for (int nt = 0; nt < 8; nt++)
#pragma unroll
            for (int e = 0; e < 4; e++) s[nt][e] = 0.f;

#pragma unroll
        for (int ks = 0; ks < 8; ks++) {
            uint32_t qhf[4], qlf[4];
            uint32_t addrA = sb + FL_QH + (uint32_t)((w * 16 + (lane & 15)) * 272)
                               + (uint32_t)(ks * 32 + (lane >> 4) * 16);
            ldsm4(addrA,                   qhf);
            ldsm4(addrA + (FL_QL - FL_QH), qlf);
            uint32_t bhf[4][4], blf[4][4];
#pragma unroll
            for (int ng = 0; ng < 4; ng++) {
                int row = ng * 16 + ((lane >> 4) << 3) + (lane & 7);
                uint32_t addrB = sb + FL_KH + (uint32_t)(row * 272)
                                   + (uint32_t)(ks * 32 + ((lane >> 3) & 1) * 16);
                ldsm4(addrB,                   bhf[ng]);
                ldsm4(addrB + (FL_KL - FL_KH), blf[ng]);
            }
#pragma unroll
            for (int nt = 0; nt < 8; nt++) {
                int ng = nt >> 1, o = (nt & 1) * 2;
                mma_bf16(s[nt], qhf, bhf[ng][o], bhf[ng][o + 1]);
                mma_bf16(s[nt], qhf, blf[ng][o], blf[ng][o + 1]);
                mma_bf16(s[nt], qlf, bhf[ng][o], bhf[ng][o + 1]);
            }
        }
        __syncthreads();
        if (it < 15) loadK(it + 1);

        const int j = it * 2;
        float rh0a = rhS[r0 * 34 + j];
        float rh0b = rhS[r0 * 34 + j + 1];
        float rh1a = rhS[r1 * 34 + j];
        float rh1b = rhS[r1 * 34 + j + 1];

        float mx0 = m0, mx1 = m1;
#pragma unroll
        for (int nt = 0; nt < 8; nt++) {
            const float rh0 = (nt < 4) ? rh0a : rh0b;
            const float rh1 = (nt < 4) ? rh1a : rh1b;
            const int i2 = (nt & 3) * 2;
            s[nt][0] += rw0[i2]     + rh0;
            s[nt][1] += rw0[i2 + 1] + rh0;
            s[nt][2] += rw1[i2]     + rh1;
            s[nt][3] += rw1[i2 + 1] + rh1;
            mx0 = fmaxf(mx0, fmaxf(s[nt][0], s[nt][1]));
            mx1 = fmaxf(mx1, fmaxf(s[nt][2], s[nt][3]));
        }
        mx0 = fmaxf(mx0, __shfl_xor_sync(0xffffffffu, mx0, 1));
        mx0 = fmaxf(mx0, __shfl_xor_sync(0xffffffffu, mx0, 2));
        mx1 = fmaxf(mx1, __shfl_xor_sync(0xffffffffu, mx1, 1));
        mx1 = fmaxf(mx1, __shfl_xor_sync(0xffffffffu, mx1, 2));

        float a0 = exp2f((m0 - mx0) * L2E);
        float a1 = exp2f((m1 - mx1) * L2E);
        m0 = mx0; m1 = mx1;

        float s0 = 0.f, s1 = 0.f;
#pragma unroll
        for (int nt = 0; nt < 8; nt++) {
            s[nt][0] = exp2f((s[nt][0] - m0) * L2E);
            s[nt][1] = exp2f((s[nt][1] - m0) * L2E);
            s[nt][2] = exp2f((s[nt][2] - m1) * L2E);
            s[nt][3] = exp2f((s[nt][3] - m1) * L2E);
            s0 += s[nt][0] + s[nt][1];
            s1 += s[nt][2] + s[nt][3];
        }
        s0 += __shfl_xor_sync(0xffffffffu, s0, 1);
        s0 += __shfl_xor_sync(0xffffffffu, s0, 2);
        s1 += __shfl_xor_sync(0xffffffffu, s1, 1);
        s1 += __shfl_xor_sync(0xffffffffu, s1, 2);
        l0 = l0 * a0 + s0;
        l1 = l1 * a1 + s1;

#pragma unroll
        for (int d = 0; d < 16; d++) {
            O[d][0] *= a0; O[d][1] *= a0;
            O[d][2] *= a1; O[d][3] *= a1;
        }

        if (it < 15) { CP_WAIT1(); } else { CP_WAIT0(); }
        __syncthreads();

#pragma unroll
        for (int ks = 0; ks < 4; ks++) {
            uint32_t pah[4], pal[4];
            {
                __nv_bfloat16 h00,l00,h01,l01,h02,l02,h03,l03;
                __nv_bfloat16 h10,l10,h11,l11,h12,l12,h13,l13;
                bsplit(s[2*ks][0],   h00, l00); bsplit(s[2*ks][1],   h01, l01);
                bsplit(s[2*ks][2],   h02, l02); bsplit(s[2*ks][3],   h03, l03);
                bsplit(s[2*ks+1][0], h10, l10); bsplit(s[2*ks+1][1], h11, l11);
                bsplit(s[2*ks+1][2], h12, l12); bsplit(s[2*ks+1][3], h13, l13);
                pah[0] = packbf(h00, h01); pah[1] = packbf(h02, h03);
                pah[2] = packbf(h10, h11); pah[3] = packbf(h12, h13);
                pal[0] = packbf(l00, l01); pal[1] = packbf(l02, l03);
                pal[2] = packbf(l10, l11); pal[3] = packbf(l12, l13);
            }
            uint32_t vrow = (uint32_t)(ks * 16 + (lane & 7) + (((lane >> 3) & 1) << 3));
            uint32_t vcb  = (uint32_t)((lane >> 4) << 4);
#pragma unroll
            for (int dg = 0; dg < 8; dg++) {
                uint32_t addrV = sb + FL_VH + vrow * 272 + (uint32_t)(dg * 32) + vcb;
                uint32_t vhf[4], vlf[4];
                ldsm4t(addrV,                   vhf);
                ldsm4t(addrV + (FL_VL - FL_VH), vlf);
#pragma unroll
                for (int hf = 0; hf < 2; hf++) {
                    int dnt = dg * 2 + hf, o = hf * 2;
                    mma_bf16(O[dnt], pah, vhf[o], vhf[o + 1]);
                    mma_bf16(O[dnt], pah, vlf[o], vlf[o + 1]);
                    mma_bf16(O[dnt], pal, vhf[o], vhf[o + 1]);
                }
            }
        }
        __syncthreads();
        if (it < 15) loadV(it + 1);
    }

    float inv0 = 1.0f / l0, inv1 = 1.0f / l1;
    size_t row0g = (size_t)((b << 10) + lq0) * 512 + hh * 128;
    size_t row1g = (size_t)((b << 10) + lq1) * 512 + hh * 128;
#pragma unroll
    for (int d = 0; d < 16; d++) {
        int col = d * 8 + cp;
        __nv_bfloat16 h0, lo0, h1, lo1;
        bsplit(O[d][0] * inv0, h0, lo0); bsplit(O[d][1] * inv0, h1, lo1);
        *(__nv_bfloat162*)&aoh[row0g + col] = __nv_bfloat162(h0, h1);
        *(__nv_bfloat162*)&aol[row0g + col] = __nv_bfloat162(lo0, lo1);
        bsplit(O[d][2] * inv1, h0, lo0); bsplit(O[d][3] * inv1, h1, lo1);
        *(__nv_bfloat162*)&aoh[row1g + col] = __nv_bfloat162(h0, h1);
        *(__nv_bfloat162*)&aol[row1g + col] = __nv_bfloat162(lo0, lo1);
    }
}

// ---------------------------------------------------------------------------
// x -> bf16 hi/lo split
// ---------------------------------------------------------------------------
__global__ __launch_bounds__(256) void splitx(const float* __restrict__ x,
                                              __nv_bfloat16* __restrict__ xh,
                                              __nv_bfloat16* __restrict__ xl, int n4)
{
    for (int i = blockIdx.x * 256 + threadIdx.x; i < n4; i += gridDim.x * 256) {
        float4 v = ((const float4*)x)[i];
        __nv_bfloat16 h0,l0,h1,l1,h2,l2,h3,l3;
        bsplit(v.x,h0,l0); bsplit(v.y,h1,l1); bsplit(v.z,h2,l2); bsplit(v.w,h3,l3);
        ((__nv_bfloat162*)xh)[i*2]   = __nv_bfloat162(h0,h1);
        ((__nv_bfloat162*)xh)[i*2+1] = __nv_bfloat162(h2,h3);
        ((__nv_bfloat162*)xl)[i*2]   = __nv_bfloat162(l0,l1);
        ((__nv_bfloat162*)xl)[i*2+1] = __nv_bfloat162(l2,l3);
    }
}

// ---------------------------------------------------------------------------
// Merged weight prep: z<4 -> transpose+split weight z; z==4 -> pos tables.
// ---------------------------------------------------------------------------
__global__ void wprep(const float* __restrict__ Wq, const float* __restrict__ Wk,
                      const float* __restrict__ Wv, const float* __restrict__ Wo,
                      const float* __restrict__ pew, const float* __restrict__ peh,
                      __nv_bfloat16* __restrict__ wqh, __nv_bfloat16* __restrict__ wql,
                      __nv_bfloat16* __restrict__ wkh, __nv_bfloat16* __restrict__ wkl,
                      __nv_bfloat16* __restrict__ wvh, __nv_bfloat16* __restrict__ wvl,
                      __nv_bfloat16* __restrict__ woh, __nv_bfloat16* __restrict__ wol,
                      __nv_bfloat16* __restrict__ pbh, __nv_bfloat16* __restrict__ pbl)
{
    const int zz = blockIdx.z;
    if (zz < 4) {
        const float* W = zz == 0 ? Wq : zz == 1 ? Wk : zz == 2 ? Wv : Wo;
        __nv_bfloat16* th = zz == 0 ? wqh : zz == 1 ? wkh : zz == 2 ? wvh : woh;
        __nv_bfloat16* tl = zz == 0 ? wql : zz == 1 ? wkl : zz == 2 ? wvl : wol;
        __shared__ float t[32][33];
        int x = blockIdx.x * 32 + threadIdx.x;
        int y = blockIdx.y * 32 + threadIdx.y;
#pragma unroll
        for (int j = 0; j < 32; j += 8)
            t[threadIdx.y + j][threadIdx.x] = W[(size_t)(y + j) * 512 + x];
        __syncthreads();
        int x2 = blockIdx.y * 32 + threadIdx.x;
        int y2 = blockIdx.x * 32 + threadIdx.y;
#pragma unroll
        for (int j = 0; j < 32; j += 8) {
            float val = t[threadIdx.x][threadIdx.y + j];
            __nv_bfloat16 h, l;
            bsplit(val, h, l);
            size_t o = (size_t)(y2 + j) * 512 + x2;
            th[o] = h; tl[o] = l;
        }
    } else {
        int blk = blockIdx.y * 16 + blockIdx.x;
        if (blk >= 64) return;
        int i = blk * 256 + threadIdx.y * 32 + threadIdx.x;
        int n = i >> 7, k = i & 127;
        float v = 0.f;
        if (n < NREL)                 v = pew[k * NREL + n];
        else if (n >= 64 && n < 127)  v = peh[k * NREL + (n - 64)];
        __nv_bfloat16 h, l;
        bsplit(v, h, l);
        pbh[i] = h; pbl[i] = l;
    }
}

// ---------------------------------------------------------------------------
extern "C" void kernel_launch(void* const* d_in, const int* in_sizes, int n_in,
                              void* d_out, int out_size)
{
    const float* x   = (const float*)d_in[0];
    const float* Wq  = (const float*)d_in[1];
    const float* Wk  = (const float*)d_in[2];
    const float* Wv  = (const float*)d_in[3];
    const float* Wo  = (const float*)d_in[4];
    const float* pew = (const float*)d_in[5];
    const float* peh = (const float*)d_in[6];
    float* out = (float*)d_out;

    float* rwhp;
    __nv_bfloat16 *xh,*xl,*qh,*ql,*kh,*kl,*vh,*vl,*aoh,*aol,*pbh,*pbl;
    __nv_bfloat16 *wqh,*wql,*wkh,*wkl,*wvh,*wvl,*woh,*wol;
    cudaGetSymbolAddress((void**)&rwhp, g_rwh);
    cudaGetSymbolAddress((void**)&xh,  g_xh);  cudaGetSymbolAddress((void**)&xl,  g_xl);
    cudaGetSymbolAddress((void**)&qh,  g_qh);  cudaGetSymbolAddress((void**)&ql,  g_ql);
    cudaGetSymbolAddress((void**)&kh,  g_kh);  cudaGetSymbolAddress((void**)&kl,  g_kl);
    cudaGetSymbolAddress((void**)&vh,  g_vh);  cudaGetSymbolAddress((void**)&vl,  g_vl);
    cudaGetSymbolAddress((void**)&aoh, g_aoh); cudaGetSymbolAddress((void**)&aol, g_aol);
    cudaGetSymbolAddress((void**)&pbh, g_pbh); cudaGetSymbolAddress((void**)&pbl, g_pbl);
    cudaGetSymbolAddress((void**)&wqh, g_wqh); cudaGetSymbolAddress((void**)&wql, g_wql);
    cudaGetSymbolAddress((void**)&wkh, g_wkh); cudaGetSymbolAddress((void**)&wkl, g_wkl);
    cudaGetSymbolAddress((void**)&wvh, g_wvh); cudaGetSymbolAddress((void**)&wvl, g_wvl);
    cudaGetSymbolAddress((void**)&woh, g_woh); cudaGetSymbolAddress((void**)&wol, g_wol);

    cudaFuncSetAttribute(gemm_bs,  cudaFuncAttributeMaxDynamicSharedMemorySize, GEMM_SMEM);
    cudaFuncSetAttribute(gemm_qkv, cudaFuncAttributeMaxDynamicSharedMemorySize, GEMM_SMEM);
    cudaFuncSetAttribute(flash,    cudaFuncAttributeMaxDynamicSharedMemorySize, FLASH_SMEM);

    const float scale = 0.08838834764831845f;   // 1/sqrt(128)

    // #1: input split
    splitx<<<1024, 256>>>(x, xh, xl, 8192*512/4);
    // #2: weight transposes + pos tables (merged)
    wprep<<<dim3(16, 16, 5), dim3(32, 8)>>>(Wq, Wk, Wv, Wo, pew, peh,
        wqh, wql, wkh, wkl, wvh, wvl, woh, wol, pbh, pbl);
    // #3: fused QKV projections (128 threads, 64x64 warp tiles)
    gemm_qkv<<<dim3(12, 64), 128, GEMM_SMEM>>>(xh, xl,
        wqh, wql, wkh, wkl, wvh, wvl, qh, ql, kh, kl, vh, vl, scale);
    // #4: relpos as batched GEMM: RW|RH [z, l, 128] = q[z,l,:] @ [posW|posH]
    gemm_bs<<<dim3(1, 8, 32), 128, GEMM_SMEM>>>(
        qh, ql, 512, 524288LL, 128LL,
        pbh, pbl, 128, 0, 0,
        rwhp, 128, 524288LL, 131072LL,
        4, 1.0f);
    // #5: flash attention (unchanged, proven)
    flash<<<dim3(8, 1, 32), 256, FLASH_SMEM>>>(qh, ql, kh, kl, vh, vl, rwhp, aoh, aol);
    // #6: output projection
    gemm_bs<<<dim3(4, 64, 1), 128, GEMM_SMEM>>>(
        aoh, aol, 512, 0, 0, woh, wol, 512, 0, 0,
        out, 512, 0, 0, 16, 1.0f);
}